// round 14
// baseline (speedup 1.0000x reference)
#include <cuda_runtime.h>
#include <math_constants.h>
#include <cfloat>

#define NN 8192
#define DD 128
#define TOPK 32

// Per-feature top-K, TRANSPOSED layout: g_topv[k*DD + d] = k-th largest of feature d.
__device__ __align__(16) float g_topv[TOPK * DD];
__device__ __align__(16) int   g_topi[TOPK * DD];

// Transposed x: xT[d][r] (4 MB static scratch).
__device__ __align__(16) float g_xT[DD * NN];

// float -> order-preserving uint32 (bijective; larger float => larger uint).
// For all finite floats the key is > 0, so 0u is a safe "cleared" sentinel.
__device__ __forceinline__ unsigned f2ord(float f) {
    unsigned b = __float_as_uint(f);
    return (b & 0x80000000u) ? ~b : (b | 0x80000000u);
}
__device__ __forceinline__ float ord2f(unsigned u) {
    unsigned b = (u & 0x80000000u) ? (u ^ 0x80000000u) : ~u;
    return __uint_as_float(b);
}

// ---------------------------------------------------------------------------
// Kernel 0: coalesced tiled transpose x[NN][DD] -> xT[DD][NN].
// 128-row x 32-col tiles, 256 blocks (~2 waves) to cut wave/launch overhead.
// ---------------------------------------------------------------------------
__global__ __launch_bounds__(256) void transpose_kernel(const float* __restrict__ x) {
    __shared__ float tile[128][33];
    const int c0 = blockIdx.x * 32;    // feature base
    const int r0 = blockIdx.y * 128;   // row base
    const int tx = threadIdx.x;        // 0..31
    const int ty = threadIdx.y;        // 0..7
#pragma unroll
    for (int i = 0; i < 128; i += 8)
        tile[ty + i][tx] = x[(size_t)(r0 + ty + i) * DD + c0 + tx];
    __syncthreads();
#pragma unroll
    for (int fo = 0; fo < 32; fo += 8) {
        const int f = c0 + ty + fo;
#pragma unroll
        for (int mb = 0; mb < 128; mb += 32)
            g_xT[(size_t)f * NN + r0 + mb + tx] = tile[mb + tx][ty + fo];
    }
}

// ---------------------------------------------------------------------------
// Kernel 1: per-feature top-K, barrier-light. One CTA (512 thr = 16 warps)
// per feature d, reading coalesced from xT.
// Phase A: warp w extracts sorted top-32 of its 512 rows (REDUX argmax x32,
//          winner = lowest lane holding the max; that lane clears its slot).
// Phase B: warp 0 re-argmaxes all 16*32=512 candidates (16 regs/lane).
// ---------------------------------------------------------------------------
__global__ __launch_bounds__(512) void topk_kernel() {
    const int d    = blockIdx.x;
    const int tid  = threadIdx.x;
    const int w    = tid >> 5;
    const int lane = tid & 31;

    const float* __restrict__ col = g_xT + (size_t)d * NN;

    // 16 rows per lane: row = w*512 + j*32 + lane (coalesced loads)
    unsigned v[16];
#pragma unroll
    for (int j = 0; j < 16; j++)
        v[j] = f2ord(col[w * 512 + j * 32 + lane]);

    __shared__ unsigned s_v[TOPK * 16];   // [k*16 + w]
    __shared__ int      s_i[TOPK * 16];

    // ---- Phase A: warp-local sorted top-32 (no block barriers) ----
    for (int k = 0; k < TOPK; k++) {
        // local argmax over 16 regs (track key and slot; row derived from slot)
        unsigned bk = v[0]; int bj = 0;
#pragma unroll
        for (int j = 1; j < 16; j++)
            if (v[j] > bk) { bk = v[j]; bj = j; }

        unsigned wm   = __reduce_max_sync(0xffffffffu, bk);
        unsigned ball = __ballot_sync(0xffffffffu, bk == wm);
        int      src  = __ffs(ball) - 1;          // winner lane (deterministic)
        int      brow = w * 512 + bj * 32 + lane; // this lane's candidate row
        int      wrow = __shfl_sync(0xffffffffu, brow, src);

        if (lane == 0) { s_v[k * 16 + w] = wm; s_i[k * 16 + w] = wrow; }
        // winner lane clears exactly its winning slot (static unrolled clear)
#pragma unroll
        for (int j = 0; j < 16; j++)
            if (lane == src && j == bj) v[j] = 0u;
    }
    __syncthreads();

    // ---- Phase B: warp 0 merges 512 candidates via the same idiom ----
    if (w == 0) {
        unsigned v2[16];
        int      r2[16];
#pragma unroll
        for (int j = 0; j < 16; j++) {           // bijective cover, bank = lane
            v2[j] = s_v[j * 32 + lane];
            r2[j] = s_i[j * 32 + lane];
        }
        for (int k = 0; k < TOPK; k++) {
            unsigned bk = v2[0]; int bj = 0; int br = r2[0];
#pragma unroll
            for (int j = 1; j < 16; j++)
                if (v2[j] > bk) { bk = v2[j]; bj = j; br = r2[j]; }

            unsigned wm   = __reduce_max_sync(0xffffffffu, bk);
            unsigned ball = __ballot_sync(0xffffffffu, bk == wm);
            int      src  = __ffs(ball) - 1;
            int      wrow = __shfl_sync(0xffffffffu, br, src);

            if (lane == 0) {
                g_topv[k * DD + d] = ord2f(wm);   // [k][d] table layout
                g_topi[k * DD + d] = wrow;
            }
#pragma unroll
            for (int j = 0; j < 16; j++)
                if (lane == src && j == bj) v2[j] = 0u;
        }
    }
}

// ---------------------------------------------------------------------------
// Kernel 2: probe (R10/R11-proven body, verbatim). One warp per row; lane
// owns 4 features (d = f*32+lane), advanced INTERLEAVED (MLP=4; probe k
// issued only after k-1 missed -> minimal DRAM bytes). Tables [k][d]:
// float4-coalesced staging, bank-conflict-free LDS (bank = lane).
// ---------------------------------------------------------------------------
__global__ __launch_bounds__(512) void probe_kernel(const float* __restrict__ x,
                                                    const int*   __restrict__ adj,
                                                    float*       __restrict__ out) {
    __shared__ __align__(16) float s_topv[TOPK * DD];
    __shared__ __align__(16) int   s_topi[TOPK * DD];
    {
        const float4* gv = (const float4*)g_topv;
        const int4*   gi = (const int4*)g_topi;
        float4* sv = (float4*)s_topv;
        int4*   si = (int4*)s_topi;
        for (int t = threadIdx.x; t < TOPK * DD / 4; t += blockDim.x) {
            sv[t] = gv[t];
            si[t] = gi[t];
        }
    }
    __syncthreads();

    const int warp = threadIdx.x >> 5;
    const int lane = threadIdx.x & 31;
    const int row  = blockIdx.x * 16 + warp;
    const int* __restrict__ arow = adj + (size_t)row * NN;

    int doff[4];
#pragma unroll
    for (int f = 0; f < 4; f++) doff[f] = f * 32 + lane;

    int      k[4]  = {0, 0, 0, 0};
    float    res[4];
    unsigned done = 0;
    unsigned fb   = 0;

#pragma unroll 1
    while (done != 0xFu) {
        int cc[4], a[4];
#pragma unroll
        for (int f = 0; f < 4; f++)
            if (!((done >> f) & 1))
                cc[f] = s_topi[k[f] * DD + doff[f]];
#pragma unroll
        for (int f = 0; f < 4; f++)
            if (!((done >> f) & 1))
                a[f] = arow[cc[f]];
#pragma unroll
        for (int f = 0; f < 4; f++) {
            if (!((done >> f) & 1)) {
                if (a[f] != 0) {
                    res[f] = s_topv[k[f] * DD + doff[f]];
                    done |= 1u << f;
                } else if (++k[f] == TOPK) {
                    fb   |= 1u << f;      // exact fallback (~never: p=2^-32)
                    done |= 1u << f;
                }
            }
        }
    }

    if (fb) {  // exact fallback: full masked row scan (also no-neighbor -> 0)
#pragma unroll 1
        for (int f = 0; f < 4; f++) {
            if ((fb >> f) & 1) {
                const int d = doff[f];
                float m = -FLT_MAX; int any = 0;
                for (int j = 0; j < NN; j++) {
                    if (arow[j] != 0) { any = 1; m = fmaxf(m, x[(size_t)j * DD + d]); }
                }
                res[f] = any ? m : 0.0f;
            }
        }
    }

#pragma unroll
    for (int f = 0; f < 4; f++)
        out[(size_t)row * DD + doff[f]] = res[f];
}

extern "C" void kernel_launch(void* const* d_in, const int* in_sizes, int n_in,
                              void* d_out, int out_size) {
    const float* x   = (const float*)d_in[0];
    const int*   adj = (const int*)d_in[1];
    float*       out = (float*)d_out;

    transpose_kernel<<<dim3(DD / 32, NN / 128), dim3(32, 8)>>>(x);
    topk_kernel<<<DD, 512>>>();
    probe_kernel<<<NN / 16, 512>>>(x, adj, out);
}

// round 15
// speedup vs baseline: 1.0088x; 1.0088x over previous
#include <cuda_runtime.h>
#include <math_constants.h>
#include <cfloat>

#define NN 8192
#define DD 128
#define TOPK 32

// Per-feature top-K, TRANSPOSED layout: g_topv[k*DD + d] = k-th largest of feature d.
__device__ __align__(16) float g_topv[TOPK * DD];
__device__ __align__(16) int   g_topi[TOPK * DD];

// Transposed x: xT[d][r] (4 MB static scratch).
__device__ __align__(16) float g_xT[DD * NN];

// float -> order-preserving uint32 (bijective; larger float => larger uint)
__device__ __forceinline__ unsigned f2ord(float f) {
    unsigned b = __float_as_uint(f);
    return (b & 0x80000000u) ? ~b : (b | 0x80000000u);
}
__device__ __forceinline__ float ord2f(unsigned u) {
    unsigned b = (u & 0x80000000u) ? (u ^ 0x80000000u) : ~u;
    return __uint_as_float(b);
}

// ---------------------------------------------------------------------------
// Kernel 0: coalesced 32x32 tiled transpose x[NN][DD] -> xT[DD][NN].
// R11-proven version: 1024 blocks (high occupancy; latency-bound kernel
// needs the parallelism, NOT fewer blocks).
// ---------------------------------------------------------------------------
__global__ __launch_bounds__(256) void transpose_kernel(const float* __restrict__ x) {
    __shared__ float tile[32][33];
    const int c0 = blockIdx.x * 32;   // feature base
    const int r0 = blockIdx.y * 32;   // row base
    const int tx = threadIdx.x;
    const int ty = threadIdx.y;
#pragma unroll
    for (int i = 0; i < 32; i += 8)
        tile[ty + i][tx] = x[(size_t)(r0 + ty + i) * DD + c0 + tx];
    __syncthreads();
#pragma unroll
    for (int i = 0; i < 32; i += 8)
        g_xT[(size_t)(c0 + ty + i) * NN + r0 + tx] = tile[tx][ty + i];
}

// ---------------------------------------------------------------------------
// Kernel 1: per-feature top-K selection (R11-proven REDUX block argmax),
// reading COALESCED from xT. One CTA (1024 threads) per feature d.
// ---------------------------------------------------------------------------
__global__ __launch_bounds__(1024) void topk_kernel() {
    const int d    = blockIdx.x;
    const int tid  = threadIdx.x;
    const int w    = tid >> 5;
    const int lane = tid & 31;

    const float* __restrict__ col = g_xT + (size_t)d * NN;

    unsigned v[8];
#pragma unroll
    for (int j = 0; j < 8; j++)
        v[j] = f2ord(col[j * 1024 + tid]);   // coalesced

    __shared__ unsigned s_wv[32];
    __shared__ int      s_wi[32];
    __shared__ int      s_bi;

    for (int k = 0; k < TOPK; k++) {
        unsigned bk = v[0]; int bj = 0;
#pragma unroll
        for (int j = 1; j < 8; j++)
            if (v[j] > bk) { bk = v[j]; bj = j; }
        int bi = bj * 1024 + tid;  // global row index

        unsigned wm   = __reduce_max_sync(0xffffffffu, bk);
        unsigned ball = __ballot_sync(0xffffffffu, bk == wm);
        int      src  = __ffs(ball) - 1;
        int      wbi  = __shfl_sync(0xffffffffu, bi, src);
        if (lane == 0) { s_wv[w] = wm; s_wi[w] = wbi; }
        __syncthreads();

        if (tid < 32) {
            unsigned k2 = s_wv[tid];
            int      i2 = s_wi[tid];
            unsigned wm2   = __reduce_max_sync(0xffffffffu, k2);
            unsigned ball2 = __ballot_sync(0xffffffffu, k2 == wm2);
            int      src2  = __ffs(ball2) - 1;
            int      wbi2  = __shfl_sync(0xffffffffu, i2, src2);
            if (tid == 0) {
                s_bi = wbi2;
                g_topv[k * DD + d] = ord2f(wm2);  // [k][d] table layout
                g_topi[k * DD + d] = wbi2;
            }
        }
        __syncthreads();

        int wi = s_bi;
        if ((wi & 1023) == tid) v[wi >> 10] = 0u;  // owner clears (rows unique)
    }
}

// ---------------------------------------------------------------------------
// Kernel 2: probe — SAME proven algorithm (interleaved MLP=4, minimal bytes),
// repacked for full occupancy: 256-thread blocks (8 rows each) + ushort index
// table (smem 33KB -> 24KB) => 8 blocks/SM = 64 warps theoretical (was 48).
// Value table stays float (bank-conflict-free); ushort LDS is 2-way (cheap).
// ---------------------------------------------------------------------------
__global__ __launch_bounds__(256) void probe_kernel(const float* __restrict__ x,
                                                    const int*   __restrict__ adj,
                                                    float*       __restrict__ out) {
    __shared__ __align__(16) float          s_topv[TOPK * DD];   // 16 KB
    __shared__ __align__(16) unsigned short s_topi[TOPK * DD];   //  8 KB
    {
        const float4* gv = (const float4*)g_topv;
        float4* sv = (float4*)s_topv;
        for (int t = threadIdx.x; t < TOPK * DD / 4; t += blockDim.x)
            sv[t] = gv[t];
        for (int t = threadIdx.x; t < TOPK * DD; t += blockDim.x)
            s_topi[t] = (unsigned short)g_topi[t];   // rows < 32768 fit
    }
    __syncthreads();

    const int warp = threadIdx.x >> 5;
    const int lane = threadIdx.x & 31;
    const int row  = blockIdx.x * 8 + warp;
    const int* __restrict__ arow = adj + (size_t)row * NN;

    int doff[4];
#pragma unroll
    for (int f = 0; f < 4; f++) doff[f] = f * 32 + lane;

    int      k[4]  = {0, 0, 0, 0};
    float    res[4];
    unsigned done = 0;
    unsigned fb   = 0;

#pragma unroll 1
    while (done != 0xFu) {
        int cc[4], a[4];
#pragma unroll
        for (int f = 0; f < 4; f++)
            if (!((done >> f) & 1))
                cc[f] = s_topi[k[f] * DD + doff[f]];
#pragma unroll
        for (int f = 0; f < 4; f++)
            if (!((done >> f) & 1))
                a[f] = arow[cc[f]];
#pragma unroll
        for (int f = 0; f < 4; f++) {
            if (!((done >> f) & 1)) {
                if (a[f] != 0) {
                    res[f] = s_topv[k[f] * DD + doff[f]];
                    done |= 1u << f;
                } else if (++k[f] == TOPK) {
                    fb   |= 1u << f;      // exact fallback (~never: p=2^-32)
                    done |= 1u << f;
                }
            }
        }
    }

    if (fb) {  // exact fallback: full masked row scan (also no-neighbor -> 0)
#pragma unroll 1
        for (int f = 0; f < 4; f++) {
            if ((fb >> f) & 1) {
                const int d = doff[f];
                float m = -FLT_MAX; int any = 0;
                for (int j = 0; j < NN; j++) {
                    if (arow[j] != 0) { any = 1; m = fmaxf(m, x[(size_t)j * DD + d]); }
                }
                res[f] = any ? m : 0.0f;
            }
        }
    }

#pragma unroll
    for (int f = 0; f < 4; f++)
        out[(size_t)row * DD + doff[f]] = res[f];
}

extern "C" void kernel_launch(void* const* d_in, const int* in_sizes, int n_in,
                              void* d_out, int out_size) {
    const float* x   = (const float*)d_in[0];
    const int*   adj = (const int*)d_in[1];
    float*       out = (float*)d_out;

    transpose_kernel<<<dim3(DD / 32, NN / 32), dim3(32, 8)>>>(x);
    topk_kernel<<<DD, 1024>>>();
    probe_kernel<<<NN / 8, 256>>>(x, adj, out);
}

// round 17
// speedup vs baseline: 1.3017x; 1.2903x over previous
#include <cuda_runtime.h>
#include <math_constants.h>
#include <cfloat>

#define NN 8192
#define DD 128
#define TOPK 32

// Per-feature top-K, TRANSPOSED layout: g_topv[k*DD + d] = k-th largest of feature d.
__device__ __align__(16) float g_topv[TOPK * DD];
__device__ __align__(16) int   g_topi[TOPK * DD];

// Transposed x: xT[d][r] (4 MB static scratch).
__device__ __align__(16) float g_xT[DD * NN];

// float -> order-preserving uint32 (bijective; larger float => larger uint)
__device__ __forceinline__ unsigned f2ord(float f) {
    unsigned b = __float_as_uint(f);
    return (b & 0x80000000u) ? ~b : (b | 0x80000000u);
}
__device__ __forceinline__ float ord2f(unsigned u) {
    unsigned b = (u & 0x80000000u) ? (u ^ 0x80000000u) : ~u;
    return __uint_as_float(b);
}

// ---------------------------------------------------------------------------
// Kernel 0: coalesced 32x32 tiled transpose x[NN][DD] -> xT[DD][NN].
// Removes the 32x L2 amplification of topk's column-strided reads.
// ---------------------------------------------------------------------------
__global__ __launch_bounds__(256) void transpose_kernel(const float* __restrict__ x) {
    __shared__ float tile[32][33];
    const int c0 = blockIdx.x * 32;   // feature base
    const int r0 = blockIdx.y * 32;   // row base
    const int tx = threadIdx.x;
    const int ty = threadIdx.y;
#pragma unroll
    for (int i = 0; i < 32; i += 8)
        tile[ty + i][tx] = x[(size_t)(r0 + ty + i) * DD + c0 + tx];
    __syncthreads();
#pragma unroll
    for (int i = 0; i < 32; i += 8)
        g_xT[(size_t)(c0 + ty + i) * NN + r0 + tx] = tile[tx][ty + i];
}

// ---------------------------------------------------------------------------
// Kernel 1: per-feature top-K selection (REDUX block argmax), reading
// COALESCED from xT. One CTA (1024 threads) per feature d.
// ---------------------------------------------------------------------------
__global__ __launch_bounds__(1024) void topk_kernel() {
    const int d    = blockIdx.x;
    const int tid  = threadIdx.x;
    const int w    = tid >> 5;
    const int lane = tid & 31;

    const float* __restrict__ col = g_xT + (size_t)d * NN;

    unsigned v[8];
#pragma unroll
    for (int j = 0; j < 8; j++)
        v[j] = f2ord(col[j * 1024 + tid]);   // coalesced

    __shared__ unsigned s_wv[32];
    __shared__ int      s_wi[32];
    __shared__ int      s_bi;

    for (int k = 0; k < TOPK; k++) {
        // thread-local argmax over 8 register slots
        unsigned bk = v[0]; int bj = 0;
#pragma unroll
        for (int j = 1; j < 8; j++)
            if (v[j] > bk) { bk = v[j]; bj = j; }
        int bi = bj * 1024 + tid;  // global row index

        // warp argmax via REDUX + ballot (deterministic: lowest lane wins ties)
        unsigned wm   = __reduce_max_sync(0xffffffffu, bk);
        unsigned ball = __ballot_sync(0xffffffffu, bk == wm);
        int      src  = __ffs(ball) - 1;
        int      wbi  = __shfl_sync(0xffffffffu, bi, src);
        if (lane == 0) { s_wv[w] = wm; s_wi[w] = wbi; }
        __syncthreads();

        if (tid < 32) {
            unsigned k2 = s_wv[tid];
            int      i2 = s_wi[tid];
            unsigned wm2   = __reduce_max_sync(0xffffffffu, k2);
            unsigned ball2 = __ballot_sync(0xffffffffu, k2 == wm2);
            int      src2  = __ffs(ball2) - 1;
            int      wbi2  = __shfl_sync(0xffffffffu, i2, src2);
            if (tid == 0) {
                s_bi = wbi2;
                g_topv[k * DD + d] = ord2f(wm2);  // transposed table layout
                g_topi[k * DD + d] = wbi2;
            }
        }
        __syncthreads();

        // owner of the winning row clears its register slot (rows unique)
        int wi = s_bi;
        if ((wi & 1023) == tid) v[wi >> 10] = 0u;  // 0 < f2ord of any finite float
    }
}

// ---------------------------------------------------------------------------
// Kernel 2: probe (proven body). One warp per row; lane owns 4 features
// (d = f*32+lane), advanced INTERLEAVED (MLP=4; probe k issued only after
// k-1 missed -> minimal DRAM bytes). Tables [k][d] in gmem:
// float4-coalesced staging, bank-conflict-free LDS (bank = lane).
// ---------------------------------------------------------------------------
__global__ __launch_bounds__(512) void probe_kernel(const float* __restrict__ x,
                                                    const int*   __restrict__ adj,
                                                    float*       __restrict__ out) {
    __shared__ __align__(16) float s_topv[TOPK * DD];
    __shared__ __align__(16) int   s_topi[TOPK * DD];
    {
        const float4* gv = (const float4*)g_topv;
        const int4*   gi = (const int4*)g_topi;
        float4* sv = (float4*)s_topv;
        int4*   si = (int4*)s_topi;
        for (int t = threadIdx.x; t < TOPK * DD / 4; t += blockDim.x) {
            sv[t] = gv[t];
            si[t] = gi[t];
        }
    }
    __syncthreads();

    const int warp = threadIdx.x >> 5;
    const int lane = threadIdx.x & 31;
    const int row  = blockIdx.x * 16 + warp;
    const int* __restrict__ arow = adj + (size_t)row * NN;

    int doff[4];
#pragma unroll
    for (int f = 0; f < 4; f++) doff[f] = f * 32 + lane;

    int      k[4]  = {0, 0, 0, 0};
    float    res[4];
    unsigned done = 0;
    unsigned fb   = 0;

#pragma unroll 1
    while (done != 0xFu) {
        int cc[4], a[4];
#pragma unroll
        for (int f = 0; f < 4; f++)
            if (!((done >> f) & 1))
                cc[f] = s_topi[k[f] * DD + doff[f]];
#pragma unroll
        for (int f = 0; f < 4; f++)
            if (!((done >> f) & 1))
                a[f] = arow[cc[f]];
#pragma unroll
        for (int f = 0; f < 4; f++) {
            if (!((done >> f) & 1)) {
                if (a[f] != 0) {
                    res[f] = s_topv[k[f] * DD + doff[f]];
                    done |= 1u << f;
                } else if (++k[f] == TOPK) {
                    fb   |= 1u << f;      // exact fallback (~never: p=2^-32)
                    done |= 1u << f;
                }
            }
        }
    }

    if (fb) {  // exact fallback: full masked row scan (also no-neighbor -> 0)
#pragma unroll 1
        for (int f = 0; f < 4; f++) {
            if ((fb >> f) & 1) {
                const int d = doff[f];
                float m = -FLT_MAX; int any = 0;
                for (int j = 0; j < NN; j++) {
                    if (arow[j] != 0) { any = 1; m = fmaxf(m, x[(size_t)j * DD + d]); }
                }
                res[f] = any ? m : 0.0f;
            }
        }
    }

#pragma unroll
    for (int f = 0; f < 4; f++)
        out[(size_t)row * DD + doff[f]] = res[f];
}

extern "C" void kernel_launch(void* const* d_in, const int* in_sizes, int n_in,
                              void* d_out, int out_size) {
    const float* x   = (const float*)d_in[0];
    const int*   adj = (const int*)d_in[1];
    float*       out = (float*)d_out;

    transpose_kernel<<<dim3(DD / 32, NN / 32), dim3(32, 8)>>>(x);
    topk_kernel<<<DD, 1024>>>();
    probe_kernel<<<NN / 16, 512>>>(x, adj, out);
}